// round 16
// baseline (speedup 1.0000x reference)
#include <cuda_runtime.h>

// f (32,512,512) f32, K (5,5,512,512) f32, dt (32,) -> out = relu(f + dt * conv_unshared5x5(f, K))
#define BATCH 32
#define H 512
#define W 512
#define HW (H * W)
#define HALO 2

// R4 compute economics (tile 32x8, 128 threads, VY=2, batch-float4 smem, 50 K
// taps in registers once per tile) + fine-grained double-buffered staging:
// 8 sub-stages x 4 batches; group s+1 is prefetched into registers and stored
// to the alternate smem buffer while group s computes. One sync per sub-stage.
#define TILE_X 32
#define TILE_Y 8
#define SM_ROWS 12
#define SM_COLS 36
#define NPOS (SM_ROWS * SM_COLS)   // 432
#define NGROUP 8                   // 8 groups x 4 batches = 32

#define FMA4(acc, fv, kk)              \
    acc.x = fmaf(fv.x, kk, acc.x);     \
    acc.y = fmaf(fv.y, kk, acc.y);     \
    acc.z = fmaf(fv.z, kk, acc.z);     \
    acc.w = fmaf(fv.w, kk, acc.w);

__global__ __launch_bounds__(128, 5) void op2d_kernel(
    const float* __restrict__ f,
    const float* __restrict__ Kk,
    const float* __restrict__ dt,
    float* __restrict__ out)
{
    __shared__ float4 fs[2][SM_ROWS][SM_COLS];   // 2 x 6912 B = 13824 B
    __shared__ __align__(16) float dts[BATCH];

    const int tid = threadIdx.x;
    const int tx = tid & 31;
    const int ty = tid >> 5;
    const int tileX = blockIdx.x * TILE_X;
    const int tileY = blockIdx.y * TILE_Y;

    if (tid < BATCH) dts[tid] = dt[tid];

    const int y0 = tileY + 2 * ty;
    const int x  = tileX + tx;
    const int ry = 2 * ty;

    // ---- prefetch helpers (indices recomputed inline; pf = 4 float4) ----
    float4 pf[4];
    auto ldg_group = [&](int b) {
        #pragma unroll
        for (int it = 0; it < 4; it++) {
            const int p = tid + it * 128;
            if (p < NPOS) {
                const int r = p / SM_COLS;
                const int c = p - r * SM_COLS;
                const int gy = tileY + r - HALO;
                const int gx = tileX + c - HALO;
                const bool in = ((unsigned)gy < (unsigned)H) & ((unsigned)gx < (unsigned)W);
                const float* fp = f + ((b * 4) * HW + gy * W + gx);
                pf[it].x = in ? __ldg(fp + 0 * HW) : 0.0f;
                pf[it].y = in ? __ldg(fp + 1 * HW) : 0.0f;
                pf[it].z = in ? __ldg(fp + 2 * HW) : 0.0f;
                pf[it].w = in ? __ldg(fp + 3 * HW) : 0.0f;
            }
        }
    };
    auto sts_group = [&](int s) {
        const int buf = s & 1;
        #pragma unroll
        for (int it = 0; it < 4; it++) {
            const int p = tid + it * 128;
            if (p < NPOS) {
                const int r = p / SM_COLS;
                const int c = p - r * SM_COLS;
                fs[buf][r][c] = pf[it];
            }
        }
    };

    // ---- prologue: group 0 staged; group 1 in flight ----
    ldg_group(0);
    sts_group(0);
    ldg_group(1);

    // 2 x 25 per-pixel kernel taps in registers, once per tile (overlaps LDGs).
    float k0[25], k1[25];
    #pragma unroll
    for (int t = 0; t < 25; t++) {
        k0[t] = __ldg(&Kk[(t * H + y0)     * W + x]);
        k1[t] = __ldg(&Kk[(t * H + y0 + 1) * W + x]);
    }

    float* outp = out + y0 * W + x;

    #pragma unroll 1
    for (int s = 0; s < NGROUP; s++) {
        __syncthreads();   // buf[s&1] (stored last iter / prologue) visible;
                           // all threads done computing group s-1
        // Stage ahead: STS group s+1 into the buffer compute(s-1) just vacated,
        // then launch group s+2's LDGs to fly during compute(s).
        if (s + 1 < NGROUP) {
            sts_group(s + 1);
            if (s + 2 < NGROUP) ldg_group(s + 2);
        }

        // ---- compute group s (4 batches) ----
        const int pb = s & 1;
        float4 a0 = make_float4(0.f, 0.f, 0.f, 0.f);
        float4 a1 = make_float4(0.f, 0.f, 0.f, 0.f);
        #pragma unroll
        for (int r = 0; r < 6; r++) {
            float4 fv0 = fs[pb][ry + r][tx + 0];
            float4 fv1 = fs[pb][ry + r][tx + 1];
            float4 fv2 = fs[pb][ry + r][tx + 2];
            float4 fv3 = fs[pb][ry + r][tx + 3];
            float4 fv4 = fs[pb][ry + r][tx + 4];
            if (r < 5) {
                FMA4(a0, fv0, k0[r * 5 + 0]);
                FMA4(a0, fv1, k0[r * 5 + 1]);
                FMA4(a0, fv2, k0[r * 5 + 2]);
                FMA4(a0, fv3, k0[r * 5 + 3]);
                FMA4(a0, fv4, k0[r * 5 + 4]);
            }
            if (r >= 1) {
                FMA4(a1, fv0, k1[(r - 1) * 5 + 0]);
                FMA4(a1, fv1, k1[(r - 1) * 5 + 1]);
                FMA4(a1, fv2, k1[(r - 1) * 5 + 2]);
                FMA4(a1, fv3, k1[(r - 1) * 5 + 3]);
                FMA4(a1, fv4, k1[(r - 1) * 5 + 4]);
            }
        }

        const int b = s * 4;
        const float4 dt4 = *(const float4*)&dts[b];
        const float4 fc0 = fs[pb][ry + HALO][tx + HALO];
        const float4 fc1 = fs[pb][ry + HALO + 1][tx + HALO];

        float* o = outp + b * HW;
        o[0] = fmaxf(fmaf(a0.x, dt4.x, fc0.x), 0.0f);
        o[W] = fmaxf(fmaf(a1.x, dt4.x, fc1.x), 0.0f);
        o += HW;
        o[0] = fmaxf(fmaf(a0.y, dt4.y, fc0.y), 0.0f);
        o[W] = fmaxf(fmaf(a1.y, dt4.y, fc1.y), 0.0f);
        o += HW;
        o[0] = fmaxf(fmaf(a0.z, dt4.z, fc0.z), 0.0f);
        o[W] = fmaxf(fmaf(a1.z, dt4.z, fc1.z), 0.0f);
        o += HW;
        o[0] = fmaxf(fmaf(a0.w, dt4.w, fc0.w), 0.0f);
        o[W] = fmaxf(fmaf(a1.w, dt4.w, fc1.w), 0.0f);
    }
}

extern "C" void kernel_launch(void* const* d_in, const int* in_sizes, int n_in,
                              void* d_out, int out_size)
{
    const float* f  = (const float*)d_in[0];
    const float* Kk = (const float*)d_in[1];
    const float* dt = (const float*)d_in[2];
    float* out = (float*)d_out;

    dim3 grid(W / TILE_X, H / TILE_Y);  // (16, 64) = 1024 blocks
    dim3 block(128);
    op2d_kernel<<<grid, block>>>(f, Kk, dt, out);
}